// round 7
// baseline (speedup 1.0000x reference)
#include <cuda_runtime.h>
#include <math.h>

#define NROWS 8192
#define DDIM  256
#define MARGIN 0.3f

#define BM 128
#define BN 128
#define BK 16
#define TM 8
#define TN 8
#define LDS_STRIDE 132   // 132 floats = 528 B; 528 % 16 == 0 -> aligned float4 rows

typedef unsigned long long u64;

// ---- packed f32x2 helpers (sm_100+ base ISA, not 'a'-gated) ----
static __device__ __forceinline__ u64 pk2(float lo, float hi) {
    u64 r;
    asm("mov.b64 %0, {%1, %2};" : "=l"(r) : "f"(lo), "f"(hi));
    return r;
}
static __device__ __forceinline__ void unpk2(float& lo, float& hi, u64 v) {
    asm("mov.b64 {%0, %1}, %2;" : "=f"(lo), "=f"(hi) : "l"(v));
}
static __device__ __forceinline__ void fma2(u64& d, u64 a, u64 b) {
    asm("fma.rn.f32x2 %0, %1, %2, %0;" : "+l"(d) : "l"(a), "l"(b));
}

// Scratch (device globals: no allocation allowed in kernel_launch)
__device__ float        g_sq[NROWS];
__device__ unsigned int g_ap[NROWS];   // float bits, running max (dist >= 0)
__device__ unsigned int g_an[NROWS];   // float bits, running min
__device__ int          g_tgt[NROWS];  // canonicalized int32 targets
__device__ int          g_is32;        // 1 if targets buffer is int32, 0 if int64

// ---------------------------------------------------------------------------
__global__ void init_kernel() { g_is32 = 0; }

// row squared norms + reduction-array init + targets dtype detection
__global__ void prep_kernel(const float* __restrict__ x, const int* __restrict__ t32)
{
    int row  = blockIdx.x * 8 + (threadIdx.x >> 5);
    int lane = threadIdx.x & 31;
    const float* xr = x + (size_t)row * DDIM;
    float s = 0.f;
#pragma unroll
    for (int k = lane; k < DDIM; k += 32) {
        float v = xr[k];
        s = fmaf(v, v, s);
    }
#pragma unroll
    for (int o = 16; o; o >>= 1) s += __shfl_xor_sync(0xffffffffu, s, o);
    if (lane == 0) {
        g_sq[row] = s;
        g_ap[row] = 0u;           // 0.0f
        g_an[row] = 0x7f800000u;  // +inf
        if (row < 2048 && t32[2 * row + 1] != 0) atomicOr(&g_is32, 1);
    }
}

__global__ void convert_kernel(const void* __restrict__ tgt)
{
    int i = blockIdx.x * 256 + threadIdx.x;
    if (i < NROWS) {
        if (g_is32) g_tgt[i] = ((const int*)tgt)[i];
        else        g_tgt[i] = (int)((const long long*)tgt)[i];
    }
}

// ---------------------------------------------------------------------------
// Fused tile GEMM (X @ X^T), upper-triangular blocks only, FFMA2 inner loop.
// Each off-diagonal tile feeds BOTH row-side and col-side max/min reductions.
// ---------------------------------------------------------------------------
__global__ __launch_bounds__(256, 2)
void tile_kernel(const float* __restrict__ x)
{
    const int bx = blockIdx.x;   // column block
    const int by = blockIdx.y;   // row block
    if (by > bx) return;         // symmetry: upper triangle only
    const bool diag = (bx == by);

    __shared__ float As[2][BK][LDS_STRIDE];
    __shared__ float Bs[2][BK][LDS_STRIDE];
    __shared__ float        sqA[BM];
    __shared__ float        sqB[BN];
    __shared__ int          tA[BM];
    __shared__ int          tB[BN];
    __shared__ unsigned int apC[BN];
    __shared__ unsigned int anC[BN];

    const int r0  = by * BM;
    const int c0  = bx * BN;
    const int tid = threadIdx.x;
    const int tx  = tid & 15;
    const int ty  = tid >> 4;

    if (tid < 128) {
        sqA[tid] = g_sq[r0 + tid];
        tA[tid]  = g_tgt[r0 + tid];
        apC[tid] = 0u;
        anC[tid] = 0x7f800000u;
    } else {
        int t = tid - 128;
        sqB[t] = g_sq[c0 + t];
        tB[t]  = g_tgt[c0 + t];
    }

    // Global-load mapping: each thread loads 2 float4 per tile (A and B each)
    const int lrow = tid >> 2;          // 0..63
    const int lcol = (tid & 3) * 4;     // 0,4,8,12

    const float* Abase = x + (size_t)(r0 + lrow) * DDIM + lcol;
    const float* Bbase = x + (size_t)(c0 + lrow) * DDIM + lcol;

    // packed accumulators: acc2[i][jp] = {dot(i,2jp), dot(i,2jp+1)}
    u64 acc2[TM][TN / 2];
#pragma unroll
    for (int i = 0; i < TM; i++)
#pragma unroll
        for (int jp = 0; jp < TN / 2; jp++) acc2[i][jp] = 0ull;

    // preload + store chunk 0 into buffer 0
    float4 a0 = *(const float4*)(Abase);
    float4 a1 = *(const float4*)(Abase + (size_t)64 * DDIM);
    float4 b0 = *(const float4*)(Bbase);
    float4 b1 = *(const float4*)(Bbase + (size_t)64 * DDIM);

    As[0][lcol + 0][lrow]      = a0.x;
    As[0][lcol + 1][lrow]      = a0.y;
    As[0][lcol + 2][lrow]      = a0.z;
    As[0][lcol + 3][lrow]      = a0.w;
    As[0][lcol + 0][lrow + 64] = a1.x;
    As[0][lcol + 1][lrow + 64] = a1.y;
    As[0][lcol + 2][lrow + 64] = a1.z;
    As[0][lcol + 3][lrow + 64] = a1.w;
    Bs[0][lcol + 0][lrow]      = b0.x;
    Bs[0][lcol + 1][lrow]      = b0.y;
    Bs[0][lcol + 2][lrow]      = b0.z;
    Bs[0][lcol + 3][lrow]      = b0.w;
    Bs[0][lcol + 0][lrow + 64] = b1.x;
    Bs[0][lcol + 1][lrow + 64] = b1.y;
    Bs[0][lcol + 2][lrow + 64] = b1.z;
    Bs[0][lcol + 3][lrow + 64] = b1.w;
    __syncthreads();

    const int NITER = DDIM / BK;
#pragma unroll 1
    for (int kk = 0; kk < NITER; ++kk) {
        const int cur = kk & 1;
        const int nxt = cur ^ 1;

        if (kk + 1 < NITER) {
            int off = (kk + 1) * BK;
            a0 = *(const float4*)(Abase + off);
            a1 = *(const float4*)(Abase + (size_t)64 * DDIM + off);
            b0 = *(const float4*)(Bbase + off);
            b1 = *(const float4*)(Bbase + (size_t)64 * DDIM + off);
        }

#pragma unroll
        for (int k = 0; k < BK; k++) {
            float4 ra0 = *(const float4*)&As[cur][k][ty * 8];
            float4 ra1 = *(const float4*)&As[cur][k][ty * 8 + 4];
            float4 rb0 = *(const float4*)&Bs[cur][k][tx * 8];
            float4 rb1 = *(const float4*)&Bs[cur][k][tx * 8 + 4];
            u64 br2[TN / 2] = { pk2(rb0.x, rb0.y), pk2(rb0.z, rb0.w),
                                pk2(rb1.x, rb1.y), pk2(rb1.z, rb1.w) };
            float ar[TM] = {ra0.x, ra0.y, ra0.z, ra0.w, ra1.x, ra1.y, ra1.z, ra1.w};
#pragma unroll
            for (int i = 0; i < TM; i++) {
                u64 a2 = pk2(ar[i], ar[i]);
#pragma unroll
                for (int jp = 0; jp < TN / 2; jp++)
                    fma2(acc2[i][jp], a2, br2[jp]);
            }
        }

        if (kk + 1 < NITER) {
            As[nxt][lcol + 0][lrow]      = a0.x;
            As[nxt][lcol + 1][lrow]      = a0.y;
            As[nxt][lcol + 2][lrow]      = a0.z;
            As[nxt][lcol + 3][lrow]      = a0.w;
            As[nxt][lcol + 0][lrow + 64] = a1.x;
            As[nxt][lcol + 1][lrow + 64] = a1.y;
            As[nxt][lcol + 2][lrow + 64] = a1.z;
            As[nxt][lcol + 3][lrow + 64] = a1.w;
            Bs[nxt][lcol + 0][lrow]      = b0.x;
            Bs[nxt][lcol + 1][lrow]      = b0.y;
            Bs[nxt][lcol + 2][lrow]      = b0.z;
            Bs[nxt][lcol + 3][lrow]      = b0.w;
            Bs[nxt][lcol + 0][lrow + 64] = b1.x;
            Bs[nxt][lcol + 1][lrow + 64] = b1.y;
            Bs[nxt][lcol + 2][lrow + 64] = b1.z;
            Bs[nxt][lcol + 3][lrow + 64] = b1.w;
        }
        __syncthreads();
    }

    // ---- epilogue: dist once; update row-side AND col-side reductions ----
    float apc[TN], anc[TN];
#pragma unroll
    for (int j = 0; j < TN; j++) { apc[j] = 0.f; anc[j] = INFINITY; }

#pragma unroll
    for (int i = 0; i < TM; i++) {
        const int r    = ty * 8 + i;
        const float sqr = sqA[r];
        const int   tr  = tA[r];
        float ap = 0.f;
        float an = INFINITY;
#pragma unroll
        for (int jp = 0; jp < TN / 2; jp++) {
            float dlo, dhi;
            unpk2(dlo, dhi, acc2[i][jp]);
            float dots[2] = {dlo, dhi};
#pragma unroll
            for (int h = 0; h < 2; h++) {
                const int j = jp * 2 + h;
                const int c = tx * 8 + j;
                float d2   = sqr + sqB[c] - 2.f * dots[h];
                float dist = sqrtf(fmaxf(d2, 1e-12f));
                if (tr == tB[c]) { ap = fmaxf(ap, dist); apc[j] = fmaxf(apc[j], dist); }
                else             { an = fminf(an, dist); anc[j] = fminf(anc[j], dist); }
            }
        }
        // row-side: reduce over the 16 tx lanes (xor stays within 16-lane half)
#pragma unroll
        for (int o = 8; o; o >>= 1) {
            ap = fmaxf(ap, __shfl_xor_sync(0xffffffffu, ap, o));
            an = fminf(an, __shfl_xor_sync(0xffffffffu, an, o));
        }
        if (tx == 0) {
            atomicMax(&g_ap[r0 + r], __float_as_uint(ap));
            atomicMin(&g_an[r0 + r], __float_as_uint(an));
        }
    }

    // col-side: smem atomics across the 16 ty groups, then 1 global atomic/col
    if (!diag) {
#pragma unroll
        for (int j = 0; j < TN; j++) {
            const int c = tx * 8 + j;
            if (apc[j] > 0.f)      atomicMax(&apC[c], __float_as_uint(apc[j]));
            if (anc[j] < INFINITY) atomicMin(&anC[c], __float_as_uint(anc[j]));
        }
        __syncthreads();
        if (tid < BN) {
            atomicMax(&g_ap[c0 + tid], apC[tid]);
            atomicMin(&g_an[c0 + tid], anC[tid]);
        }
    }
}

// ---------------------------------------------------------------------------
__global__ void final_kernel(float* __restrict__ out, int out_size)
{
    __shared__ float sl[256];
    __shared__ float sp[256];
    int tid = threadIdx.x;
    float loss = 0.f, prec = 0.f;
    for (int r = tid; r < NROWS; r += 256) {
        float ap = __uint_as_float(g_ap[r]);
        float an = __uint_as_float(g_an[r]);
        loss += fmaxf(ap - an + MARGIN, 0.f);
        prec += (an > ap) ? 1.f : 0.f;
    }
    sl[tid] = loss;
    sp[tid] = prec;
    __syncthreads();
    for (int s = 128; s; s >>= 1) {
        if (tid < s) { sl[tid] += sl[tid + s]; sp[tid] += sp[tid + s]; }
        __syncthreads();
    }
    if (tid == 0) {
        out[0] = sl[0] * (1.0f / NROWS);
        if (out_size > 1) out[1] = sp[0] * (1.0f / NROWS);
    }
}

// ---------------------------------------------------------------------------
extern "C" void kernel_launch(void* const* d_in, const int* in_sizes, int n_in,
                              void* d_out, int out_size)
{
    const float* x   = (const float*)d_in[0];
    const void*  tgt = d_in[1];
    float*       out = (float*)d_out;

    init_kernel<<<1, 1>>>();
    prep_kernel<<<NROWS / 8, 256>>>(x, (const int*)tgt);
    convert_kernel<<<NROWS / 256, 256>>>(tgt);

    dim3 grid(NROWS / BN, NROWS / BM);   // (64, 64); lower triangle exits early
    tile_kernel<<<grid, 256>>>(x);

    final_kernel<<<1, 256>>>(out, out_size);
}

// round 10
// speedup vs baseline: 3.2075x; 3.2075x over previous
#include <cuda_runtime.h>
#include <cuda_bf16.h>
#include <math.h>
#include <stdint.h>

#define NROWS 8192
#define DDIM  256
#define MARGIN 0.3f

#define BM 128
#define BN 128
#define KC  64
#define NSTAGE (DDIM / KC)   // 4

// ---- dynamic smem layout ----
#define OFF_SQA 0
#define OFF_TA  512
#define OFF_SQB 1024
#define OFF_TB  1536
#define OFF_APR 2048
#define OFF_ANR 2560
#define OFF_APC 3072
#define OFF_ANC 3584
#define OFF_TILE 4096
#define STAGE_BYTES 65536     // A_hi|A_lo|B_hi|B_lo each 128x64 bf16 = 16KB
#define A_HI 0
#define A_LO 16384
#define B_HI 32768
#define B_LO 49152
#define SMEM_TOTAL (OFF_TILE + 2 * STAGE_BYTES)   // 135168

// ---- device globals (no allocation allowed) ----
__device__ float        g_sq[NROWS];
__device__ unsigned int g_ap[NROWS];
__device__ unsigned int g_an[NROWS];
__device__ int          g_tgt[NROWS];
__device__ int          g_is32;
__device__ uint4        g_xhi4[NROWS * DDIM / 8];   // bf16 hi, 8 per uint4
__device__ uint4        g_xlo4[NROWS * DDIM / 8];   // bf16 lo

// ---- helpers ----
static __device__ __forceinline__ uint32_t smem_u32(const void* p) {
    uint32_t a;
    asm("{ .reg .u64 t; cvta.to.shared.u64 t, %1; cvt.u32.u64 %0, t; }" : "=r"(a) : "l"(p));
    return a;
}
static __device__ __forceinline__ void cp16(uint32_t saddr, const void* g) {
    asm volatile("cp.async.cg.shared.global [%0], [%1], 16;" :: "r"(saddr), "l"(g));
}
#define CP_COMMIT() asm volatile("cp.async.commit_group;" ::: "memory")
#define CP_WAIT(n)  asm volatile("cp.async.wait_group %0;" :: "n"(n) : "memory")

static __device__ __forceinline__ void ldsm4(uint32_t a, uint32_t* r) {
    asm volatile("ldmatrix.sync.aligned.m8n8.x4.shared.b16 {%0,%1,%2,%3}, [%4];"
                 : "=r"(r[0]), "=r"(r[1]), "=r"(r[2]), "=r"(r[3]) : "r"(a));
}
static __device__ __forceinline__ void mma16816(float* d, const uint32_t* a, const uint32_t* b) {
    asm volatile("mma.sync.aligned.m16n8k16.row.col.f32.bf16.bf16.f32 "
                 "{%0,%1,%2,%3}, {%4,%5,%6,%7}, {%8,%9}, {%0,%1,%2,%3};"
                 : "+f"(d[0]), "+f"(d[1]), "+f"(d[2]), "+f"(d[3])
                 : "r"(a[0]), "r"(a[1]), "r"(a[2]), "r"(a[3]), "r"(b[0]), "r"(b[1]));
}
// swizzled byte offset inside a 128x64-bf16 tile (128B rows, 16B chunks XOR row%8)
static __device__ __forceinline__ uint32_t lmoff(int r, int kc) {
    return (uint32_t)((r << 7) + ((((kc >> 3) ^ (r & 7))) << 4));
}

// ---------------------------------------------------------------------------
__global__ void init_kernel() { g_is32 = 0; }

// norms + reduction init + dtype detect + bf16 hi/lo split
__global__ void prep_kernel(const float* __restrict__ x, const int* __restrict__ t32)
{
    int row  = blockIdx.x * 8 + (threadIdx.x >> 5);
    int lane = threadIdx.x & 31;
    const float* xr = x + (size_t)row * DDIM;
    __nv_bfloat16* xh = (__nv_bfloat16*)g_xhi4;
    __nv_bfloat16* xl = (__nv_bfloat16*)g_xlo4;
    float s = 0.f;
#pragma unroll
    for (int k = lane; k < DDIM; k += 32) {
        float v = xr[k];
        s = fmaf(v, v, s);
        __nv_bfloat16 hi = __float2bfloat16(v);
        float lo = v - __bfloat162float(hi);
        xh[(size_t)row * DDIM + k] = hi;
        xl[(size_t)row * DDIM + k] = __float2bfloat16(lo);
    }
#pragma unroll
    for (int o = 16; o; o >>= 1) s += __shfl_xor_sync(0xffffffffu, s, o);
    if (lane == 0) {
        g_sq[row] = s;
        g_ap[row] = 0u;
        g_an[row] = 0x7f800000u;
        if (row < 2048 && t32[2 * row + 1] != 0) atomicOr(&g_is32, 1);
    }
}

__global__ void convert_kernel(const void* __restrict__ tgt)
{
    int i = blockIdx.x * 256 + threadIdx.x;
    if (i < NROWS) {
        if (g_is32) g_tgt[i] = ((const int*)tgt)[i];
        else        g_tgt[i] = (int)((const long long*)tgt)[i];
    }
}

// ---------------------------------------------------------------------------
// Fused HMMA (mma.sync bf16 hi/lo) GEMM tile + dist + dual row/col reductions.
// Upper-triangular blocks only; cp.async double-buffered K pipeline.
// ---------------------------------------------------------------------------
__global__ __launch_bounds__(256, 1)
void tile_kernel()
{
    const int bx = blockIdx.x;
    const int by = blockIdx.y;
    if (by > bx) return;
    const bool diag = (bx == by);

    extern __shared__ char sm[];
    const uint32_t sb = smem_u32(sm);

    const int tid  = threadIdx.x;
    const int lane = tid & 31;
    const int wid  = tid >> 5;
    const int wm   = wid & 1;     // 2 warps over M (64 rows each)
    const int wn   = wid >> 1;    // 4 warps over N (32 cols each)
    const int r0   = by * BM;
    const int c0   = bx * BN;

    // ---- issue stage 0 loads ----
    {
        const int s = 0;
#pragma unroll
        for (int t = 0; t < 4; t++) {
            int idx = tid + t * 256;
            int r = idx >> 3, c = idx & 7;
            uint32_t so = (uint32_t)((r << 7) + ((c ^ (r & 7)) << 4));
            int gA = (r0 + r) * (DDIM / 8) + s * 8 + c;
            int gB = (c0 + r) * (DDIM / 8) + s * 8 + c;
            uint32_t base = sb + OFF_TILE;
            cp16(base + A_HI + so, &g_xhi4[gA]);
            cp16(base + A_LO + so, &g_xlo4[gA]);
            cp16(base + B_HI + so, &g_xhi4[gB]);
            cp16(base + B_LO + so, &g_xlo4[gB]);
        }
        CP_COMMIT();
    }

    // ---- metadata into smem ----
    if (tid < 128) {
        ((float*)(sm + OFF_SQA))[tid]    = g_sq[r0 + tid];
        ((int*)(sm + OFF_TA))[tid]       = g_tgt[r0 + tid];
        ((float*)(sm + OFF_SQB))[tid]    = g_sq[c0 + tid];
        ((int*)(sm + OFF_TB))[tid]       = g_tgt[c0 + tid];
        ((uint32_t*)(sm + OFF_APR))[tid] = 0u;
        ((uint32_t*)(sm + OFF_ANR))[tid] = 0x7f800000u;
        ((uint32_t*)(sm + OFF_APC))[tid] = 0u;
        ((uint32_t*)(sm + OFF_ANC))[tid] = 0x7f800000u;
    }

    float acc[4][4][4];
#pragma unroll
    for (int i = 0; i < 4; i++)
#pragma unroll
        for (int j = 0; j < 4; j++)
#pragma unroll
            for (int q = 0; q < 4; q++) acc[i][j][q] = 0.f;

    // ---- mainloop over K chunks ----
#pragma unroll 1
    for (int s = 0; s < NSTAGE; s++) {
        if (s + 1 < NSTAGE) {
            const int sn = s + 1;
            uint32_t base = sb + OFF_TILE + (sn & 1) * STAGE_BYTES;
#pragma unroll
            for (int t = 0; t < 4; t++) {
                int idx = tid + t * 256;
                int r = idx >> 3, c = idx & 7;
                uint32_t so = (uint32_t)((r << 7) + ((c ^ (r & 7)) << 4));
                int gA = (r0 + r) * (DDIM / 8) + sn * 8 + c;
                int gB = (c0 + r) * (DDIM / 8) + sn * 8 + c;
                cp16(base + A_HI + so, &g_xhi4[gA]);
                cp16(base + A_LO + so, &g_xlo4[gA]);
                cp16(base + B_HI + so, &g_xhi4[gB]);
                cp16(base + B_LO + so, &g_xlo4[gB]);
            }
            CP_COMMIT();
            CP_WAIT(1);
        } else {
            CP_WAIT(0);
        }
        __syncthreads();

        const uint32_t base = sb + OFF_TILE + (s & 1) * STAGE_BYTES;
#pragma unroll
        for (int st = 0; st < 4; st++) {
            const int k0 = st * 16;
            uint32_t ah[4][4], al[4][4], bh[2][4], bl[2][4];
            const int kcA = k0 + ((lane >> 4) << 3);
            const int rA0 = wm * 64 + (lane & 15);
#pragma unroll
            for (int i = 0; i < 4; i++) {
                uint32_t off = lmoff(rA0 + i * 16, kcA);
                ldsm4(base + A_HI + off, ah[i]);
                ldsm4(base + A_LO + off, al[i]);
            }
            const int rB0 = wn * 32 + ((lane >> 4) << 3) + (lane & 7);
            const int kcB = k0 + (((lane >> 3) & 1) << 3);
#pragma unroll
            for (int jp = 0; jp < 2; jp++) {
                uint32_t off = lmoff(rB0 + jp * 16, kcB);
                ldsm4(base + B_HI + off, bh[jp]);
                ldsm4(base + B_LO + off, bl[jp]);
            }
#pragma unroll
            for (int i = 0; i < 4; i++)
#pragma unroll
                for (int j = 0; j < 4; j++) {
                    const uint32_t* bhp = &bh[j >> 1][(j & 1) * 2];
                    const uint32_t* blp = &bl[j >> 1][(j & 1) * 2];
                    mma16816(acc[i][j], ah[i], bhp);   // hi*hi
                    mma16816(acc[i][j], ah[i], blp);   // hi*lo
                    mma16816(acc[i][j], al[i], bhp);   // lo*hi
                }
        }
        __syncthreads();
    }

    // ---- epilogue ----
    const int gid = lane >> 2;
    const int tg  = lane & 3;
    const float* sqA = (const float*)(sm + OFF_SQA);
    const float* sqB = (const float*)(sm + OFF_SQB);
    const int*   tA  = (const int*)(sm + OFF_TA);
    const int*   tB  = (const int*)(sm + OFF_TB);

    float apR[8], anR[8], apC[8], anC[8];
#pragma unroll
    for (int q = 0; q < 8; q++) { apR[q] = 0.f; anR[q] = INFINITY; apC[q] = 0.f; anC[q] = INFINITY; }

#pragma unroll
    for (int i = 0; i < 4; i++) {
#pragma unroll
        for (int h = 0; h < 2; h++) {
            const int r   = wm * 64 + i * 16 + h * 8 + gid;
            const float sqr = sqA[r];
            const int   tr  = tA[r];
#pragma unroll
            for (int j = 0; j < 4; j++) {
#pragma unroll
                for (int e = 0; e < 2; e++) {
                    const int c   = wn * 32 + j * 8 + 2 * tg + e;
                    float dot  = acc[i][j][h * 2 + e];
                    float d2   = sqr + sqB[c] - 2.f * dot;
                    float dist = sqrtf(fmaxf(d2, 1e-12f));
                    if (tr == tB[c]) {
                        apR[i * 2 + h] = fmaxf(apR[i * 2 + h], dist);
                        apC[j * 2 + e] = fmaxf(apC[j * 2 + e], dist);
                    } else {
                        anR[i * 2 + h] = fminf(anR[i * 2 + h], dist);
                        anC[j * 2 + e] = fminf(anC[j * 2 + e], dist);
                    }
                }
            }
        }
    }

    // row-side: reduce over tg (lanes xor 1,2), then smem atomic per row
#pragma unroll
    for (int q = 0; q < 8; q++) {
#pragma unroll
        for (int o = 1; o <= 2; o <<= 1) {
            apR[q] = fmaxf(apR[q], __shfl_xor_sync(0xffffffffu, apR[q], o));
            anR[q] = fminf(anR[q], __shfl_xor_sync(0xffffffffu, anR[q], o));
        }
        if (tg == 0) {
            const int i = q >> 1, h = q & 1;
            const int r = wm * 64 + i * 16 + h * 8 + gid;
            atomicMax((unsigned int*)(sm + OFF_APR) + r, __float_as_uint(apR[q]));
            atomicMin((unsigned int*)(sm + OFF_ANR) + r, __float_as_uint(anR[q]));
        }
    }
    // col-side: reduce over gid (lanes xor 4,8,16), then smem atomic per col
#pragma unroll
    for (int q = 0; q < 8; q++) {
#pragma unroll
        for (int o = 4; o <= 16; o <<= 1) {
            apC[q] = fmaxf(apC[q], __shfl_xor_sync(0xffffffffu, apC[q], o));
            anC[q] = fminf(anC[q], __shfl_xor_sync(0xffffffffu, anC[q], o));
        }
        if (gid == 0) {
            const int j = q >> 1, e = q & 1;
            const int c = wn * 32 + j * 8 + 2 * tg + e;
            atomicMax((unsigned int*)(sm + OFF_APC) + c, __float_as_uint(apC[q]));
            atomicMin((unsigned int*)(sm + OFF_ANC) + c, __float_as_uint(anC[q]));
        }
    }
    __syncthreads();

    if (tid < 128) {
        atomicMax(&g_ap[r0 + tid], ((unsigned int*)(sm + OFF_APR))[tid]);
        atomicMin(&g_an[r0 + tid], ((unsigned int*)(sm + OFF_ANR))[tid]);
        if (!diag) {
            atomicMax(&g_ap[c0 + tid], ((unsigned int*)(sm + OFF_APC))[tid]);
            atomicMin(&g_an[c0 + tid], ((unsigned int*)(sm + OFF_ANC))[tid]);
        }
    }
}

// ---------------------------------------------------------------------------
__global__ void final_kernel(float* __restrict__ out, int out_size)
{
    __shared__ float sl[256];
    __shared__ float sp[256];
    int tid = threadIdx.x;
    float loss = 0.f, prec = 0.f;
    for (int r = tid; r < NROWS; r += 256) {
        float ap = __uint_as_float(g_ap[r]);
        float an = __uint_as_float(g_an[r]);
        loss += fmaxf(ap - an + MARGIN, 0.f);
        prec += (an > ap) ? 1.f : 0.f;
    }
    sl[tid] = loss;
    sp[tid] = prec;
    __syncthreads();
    for (int s = 128; s; s >>= 1) {
        if (tid < s) { sl[tid] += sl[tid + s]; sp[tid] += sp[tid + s]; }
        __syncthreads();
    }
    if (tid == 0) {
        out[0] = sl[0] * (1.0f / NROWS);
        if (out_size > 1) out[1] = sp[0] * (1.0f / NROWS);
    }
}

// ---------------------------------------------------------------------------
extern "C" void kernel_launch(void* const* d_in, const int* in_sizes, int n_in,
                              void* d_out, int out_size)
{
    const float* x   = (const float*)d_in[0];
    const void*  tgt = d_in[1];
    float*       out = (float*)d_out;

    cudaFuncSetAttribute(tile_kernel, cudaFuncAttributeMaxDynamicSharedMemorySize, SMEM_TOTAL);

    init_kernel<<<1, 1>>>();
    prep_kernel<<<NROWS / 8, 256>>>(x, (const int*)tgt);
    convert_kernel<<<NROWS / 256, 256>>>(tgt);

    dim3 grid(NROWS / BN, NROWS / BM);   // (64, 64); lower triangle exits early
    tile_kernel<<<grid, 256, SMEM_TOTAL>>>();

    final_kernel<<<1, 256>>>(out, out_size);
}

// round 12
// speedup vs baseline: 3.9144x; 1.2204x over previous
#include <cuda_runtime.h>
#include <cuda_bf16.h>
#include <math.h>
#include <stdint.h>

#define NROWS 8192
#define DDIM  256
#define MARGIN 0.3f

#define BM 128
#define BN 128
#define KC  32
#define NSTAGE (DDIM / KC)   // 8

// ---- dynamic smem layout ----
#define OFF_SQA 0
#define OFF_TA  512
#define OFF_SQB 1024
#define OFF_TB  1536
#define OFF_APR 2048
#define OFF_ANR 2560
#define OFF_APC 3072
#define OFF_ANC 3584
#define OFF_TILE 4096
// per stage: A tile 128 rows x 128B (hi chunks 0-3, lo chunks 4-7) = 16KB, B same
#define STAGE_BYTES 32768
#define A_OFF 0
#define B_OFF 16384
#define SMEM_TOTAL (OFF_TILE + 2 * STAGE_BYTES)   // 69632 -> 2 CTAs/SM

// ---- device globals (no allocation allowed) ----
__device__ float        g_sq[NROWS];
__device__ unsigned int g_ap[NROWS];
__device__ unsigned int g_an[NROWS];
__device__ int          g_tgt[NROWS];
__device__ int          g_is32;
__device__ uint4        g_xhi4[NROWS * DDIM / 8];   // bf16 hi, 8 per uint4
__device__ uint4        g_xlo4[NROWS * DDIM / 8];   // bf16 lo

// ---- helpers ----
static __device__ __forceinline__ uint32_t smem_u32(const void* p) {
    uint32_t a;
    asm("{ .reg .u64 t; cvta.to.shared.u64 t, %1; cvt.u32.u64 %0, t; }" : "=r"(a) : "l"(p));
    return a;
}
static __device__ __forceinline__ void cp16(uint32_t saddr, const void* g) {
    asm volatile("cp.async.cg.shared.global [%0], [%1], 16;" :: "r"(saddr), "l"(g));
}
#define CP_COMMIT() asm volatile("cp.async.commit_group;" ::: "memory")
#define CP_WAIT(n)  asm volatile("cp.async.wait_group %0;" :: "n"(n) : "memory")

static __device__ __forceinline__ void ldsm4(uint32_t a, uint32_t* r) {
    asm volatile("ldmatrix.sync.aligned.m8n8.x4.shared.b16 {%0,%1,%2,%3}, [%4];"
                 : "=r"(r[0]), "=r"(r[1]), "=r"(r[2]), "=r"(r[3]) : "r"(a));
}
static __device__ __forceinline__ void mma16816(float* d, const uint32_t* a, const uint32_t* b) {
    asm volatile("mma.sync.aligned.m16n8k16.row.col.f32.bf16.bf16.f32 "
                 "{%0,%1,%2,%3}, {%4,%5,%6,%7}, {%8,%9}, {%0,%1,%2,%3};"
                 : "+f"(d[0]), "+f"(d[1]), "+f"(d[2]), "+f"(d[3])
                 : "r"(a[0]), "r"(a[1]), "r"(a[2]), "r"(a[3]), "r"(b[0]), "r"(b[1]));
}
// swizzled byte offset: tile rows of 128B, chunk (16B) index 0-7 XOR (row&7)
static __device__ __forceinline__ uint32_t swz(int r, int chunk) {
    return (uint32_t)((r << 7) + ((chunk ^ (r & 7)) << 4));
}

// ---------------------------------------------------------------------------
__global__ void init_kernel() { g_is32 = 0; }

// norms + reduction init + dtype detect + bf16 hi/lo split
__global__ void prep_kernel(const float* __restrict__ x, const int* __restrict__ t32)
{
    int row  = blockIdx.x * 8 + (threadIdx.x >> 5);
    int lane = threadIdx.x & 31;
    const float* xr = x + (size_t)row * DDIM;
    __nv_bfloat16* xh = (__nv_bfloat16*)g_xhi4;
    __nv_bfloat16* xl = (__nv_bfloat16*)g_xlo4;
    float s = 0.f;
#pragma unroll
    for (int k = lane; k < DDIM; k += 32) {
        float v = xr[k];
        s = fmaf(v, v, s);
        __nv_bfloat16 hi = __float2bfloat16(v);
        float lo = v - __bfloat162float(hi);
        xh[(size_t)row * DDIM + k] = hi;
        xl[(size_t)row * DDIM + k] = __float2bfloat16(lo);
    }
#pragma unroll
    for (int o = 16; o; o >>= 1) s += __shfl_xor_sync(0xffffffffu, s, o);
    if (lane == 0) {
        g_sq[row] = s;
        g_ap[row] = 0u;
        g_an[row] = 0x7f800000u;
        if (row < 2048 && t32[2 * row + 1] != 0) atomicOr(&g_is32, 1);
    }
}

__global__ void convert_kernel(const void* __restrict__ tgt)
{
    int i = blockIdx.x * 256 + threadIdx.x;
    if (i < NROWS) {
        if (g_is32) g_tgt[i] = ((const int*)tgt)[i];
        else        g_tgt[i] = (int)((const long long*)tgt)[i];
    }
}

// ---------------------------------------------------------------------------
// Fused HMMA (mma.sync bf16 hi/lo) GEMM tile + dist + dual row/col reductions.
// Upper-triangular blocks only; cp.async double-buffered; KC=32 => 2 CTAs/SM.
// ---------------------------------------------------------------------------
__global__ __launch_bounds__(256, 2)
void tile_kernel()
{
    const int bx = blockIdx.x;
    const int by = blockIdx.y;
    if (by > bx) return;
    const bool diag = (bx == by);

    extern __shared__ char sm[];
    const uint32_t sb = smem_u32(sm);

    const int tid  = threadIdx.x;
    const int lane = tid & 31;
    const int wid  = tid >> 5;
    const int wm   = wid & 1;     // 2 warps over M (64 rows each)
    const int wn   = wid >> 1;    // 4 warps over N (32 cols each)
    const int r0   = by * BM;
    const int c0   = bx * BN;

    // ---- issue stage 0 loads (8 cp16/thread: 4 for A, 4 for B) ----
    {
        uint32_t base = sb + OFF_TILE;
#pragma unroll
        for (int t = 0; t < 4; t++) {
            int idx = tid + t * 256;          // 0..1023
            int r = idx >> 3, c8 = idx & 7;   // c8: 0-3 hi, 4-7 lo
            uint32_t so = swz(r, c8);
            const uint4* srcA = (c8 < 4) ? &g_xhi4[(r0 + r) * (DDIM / 8) + c8]
                                         : &g_xlo4[(r0 + r) * (DDIM / 8) + (c8 - 4)];
            const uint4* srcB = (c8 < 4) ? &g_xhi4[(c0 + r) * (DDIM / 8) + c8]
                                         : &g_xlo4[(c0 + r) * (DDIM / 8) + (c8 - 4)];
            cp16(base + A_OFF + so, srcA);
            cp16(base + B_OFF + so, srcB);
        }
        CP_COMMIT();
    }

    // ---- metadata into smem ----
    if (tid < 128) {
        ((float*)(sm + OFF_SQA))[tid]    = g_sq[r0 + tid];
        ((int*)(sm + OFF_TA))[tid]       = g_tgt[r0 + tid];
        ((float*)(sm + OFF_SQB))[tid]    = g_sq[c0 + tid];
        ((int*)(sm + OFF_TB))[tid]       = g_tgt[c0 + tid];
        ((uint32_t*)(sm + OFF_APR))[tid] = 0u;
        ((uint32_t*)(sm + OFF_ANR))[tid] = 0x7f800000u;
        ((uint32_t*)(sm + OFF_APC))[tid] = 0u;
        ((uint32_t*)(sm + OFF_ANC))[tid] = 0x7f800000u;
    }

    float acc[4][4][4];
#pragma unroll
    for (int i = 0; i < 4; i++)
#pragma unroll
        for (int j = 0; j < 4; j++)
#pragma unroll
            for (int q = 0; q < 4; q++) acc[i][j][q] = 0.f;

    // ---- mainloop over 8 K chunks of 32 ----
#pragma unroll 1
    for (int s = 0; s < NSTAGE; s++) {
        if (s + 1 < NSTAGE) {
            const int sn = s + 1;
            uint32_t base = sb + OFF_TILE + (sn & 1) * STAGE_BYTES;
            const int kb = sn * (KC / 8);     // uint4 offset of this K chunk
#pragma unroll
            for (int t = 0; t < 4; t++) {
                int idx = tid + t * 256;
                int r = idx >> 3, c8 = idx & 7;
                uint32_t so = swz(r, c8);
                const uint4* srcA = (c8 < 4) ? &g_xhi4[(r0 + r) * (DDIM / 8) + kb + c8]
                                             : &g_xlo4[(r0 + r) * (DDIM / 8) + kb + (c8 - 4)];
                const uint4* srcB = (c8 < 4) ? &g_xhi4[(c0 + r) * (DDIM / 8) + kb + c8]
                                             : &g_xlo4[(c0 + r) * (DDIM / 8) + kb + (c8 - 4)];
                cp16(base + A_OFF + so, srcA);
                cp16(base + B_OFF + so, srcB);
            }
            CP_COMMIT();
            CP_WAIT(1);
        } else {
            CP_WAIT(0);
        }
        __syncthreads();

        const uint32_t base = sb + OFF_TILE + (s & 1) * STAGE_BYTES;
#pragma unroll
        for (int st = 0; st < 2; st++) {      // 2 k-steps of 16 per chunk
            const int k0 = st * 16;
            // B fragments first (16 regs live)
            uint32_t bh[2][4], bl[2][4];
            const int rB0 = wn * 32 + ((lane >> 4) << 3) + (lane & 7);
            const int cB  = (k0 + (((lane >> 3) & 1) << 3)) >> 3;   // hi chunk 0..3
#pragma unroll
            for (int jp = 0; jp < 2; jp++) {
                int r = rB0 + jp * 16;
                ldsm4(base + B_OFF + swz(r, cB),     bh[jp]);
                ldsm4(base + B_OFF + swz(r, cB + 4), bl[jp]);
            }
            const int rA0 = wm * 64 + (lane & 15);
            const int cA  = (k0 + ((lane >> 4) << 3)) >> 3;
#pragma unroll
            for (int i = 0; i < 4; i++) {
                uint32_t ah[4], al[4];
                int r = rA0 + i * 16;
                ldsm4(base + A_OFF + swz(r, cA),     ah);
                ldsm4(base + A_OFF + swz(r, cA + 4), al);
#pragma unroll
                for (int j = 0; j < 4; j++) {
                    const uint32_t* bhp = &bh[j >> 1][(j & 1) * 2];
                    const uint32_t* blp = &bl[j >> 1][(j & 1) * 2];
                    mma16816(acc[i][j], ah, bhp);   // hi*hi
                    mma16816(acc[i][j], ah, blp);   // hi*lo
                    mma16816(acc[i][j], al, bhp);   // lo*hi
                }
            }
        }
        __syncthreads();
    }

    // ---- epilogue ----
    const int gid = lane >> 2;
    const int tg  = lane & 3;
    const float* sqA = (const float*)(sm + OFF_SQA);
    const float* sqB = (const float*)(sm + OFF_SQB);
    const int*   tA  = (const int*)(sm + OFF_TA);
    const int*   tB  = (const int*)(sm + OFF_TB);

    float apR[8], anR[8], apC[8], anC[8];
#pragma unroll
    for (int q = 0; q < 8; q++) { apR[q] = 0.f; anR[q] = INFINITY; apC[q] = 0.f; anC[q] = INFINITY; }

#pragma unroll
    for (int i = 0; i < 4; i++) {
#pragma unroll
        for (int h = 0; h < 2; h++) {
            const int r   = wm * 64 + i * 16 + h * 8 + gid;
            const float sqr = sqA[r];
            const int   tr  = tA[r];
#pragma unroll
            for (int j = 0; j < 4; j++) {
#pragma unroll
                for (int e = 0; e < 2; e++) {
                    const int c   = wn * 32 + j * 8 + 2 * tg + e;
                    float dot  = acc[i][j][h * 2 + e];
                    float d2   = sqr + sqB[c] - 2.f * dot;
                    float dist = sqrtf(fmaxf(d2, 1e-12f));
                    if (tr == tB[c]) {
                        apR[i * 2 + h] = fmaxf(apR[i * 2 + h], dist);
                        apC[j * 2 + e] = fmaxf(apC[j * 2 + e], dist);
                    } else {
                        anR[i * 2 + h] = fminf(anR[i * 2 + h], dist);
                        anC[j * 2 + e] = fminf(anC[j * 2 + e], dist);
                    }
                }
            }
        }
    }

    // row-side: reduce over tg (lanes xor 1,2), then smem atomic per row
#pragma unroll
    for (int q = 0; q < 8; q++) {
#pragma unroll
        for (int o = 1; o <= 2; o <<= 1) {
            apR[q] = fmaxf(apR[q], __shfl_xor_sync(0xffffffffu, apR[q], o));
            anR[q] = fminf(anR[q], __shfl_xor_sync(0xffffffffu, anR[q], o));
        }
        if (tg == 0) {
            const int i = q >> 1, h = q & 1;
            const int r = wm * 64 + i * 16 + h * 8 + gid;
            atomicMax((unsigned int*)(sm + OFF_APR) + r, __float_as_uint(apR[q]));
            atomicMin((unsigned int*)(sm + OFF_ANR) + r, __float_as_uint(anR[q]));
        }
    }
    // col-side: reduce over gid (lanes xor 4,8,16), then smem atomic per col
#pragma unroll
    for (int q = 0; q < 8; q++) {
#pragma unroll
        for (int o = 4; o <= 16; o <<= 1) {
            apC[q] = fmaxf(apC[q], __shfl_xor_sync(0xffffffffu, apC[q], o));
            anC[q] = fminf(anC[q], __shfl_xor_sync(0xffffffffu, anC[q], o));
        }
        if (gid == 0) {
            const int j = q >> 1, e = q & 1;
            const int c = wn * 32 + j * 8 + 2 * tg + e;
            atomicMax((unsigned int*)(sm + OFF_APC) + c, __float_as_uint(apC[q]));
            atomicMin((unsigned int*)(sm + OFF_ANC) + c, __float_as_uint(anC[q]));
        }
    }
    __syncthreads();

    if (tid < 128) {
        atomicMax(&g_ap[r0 + tid], ((unsigned int*)(sm + OFF_APR))[tid]);
        atomicMin(&g_an[r0 + tid], ((unsigned int*)(sm + OFF_ANR))[tid]);
        if (!diag) {
            atomicMax(&g_ap[c0 + tid], ((unsigned int*)(sm + OFF_APC))[tid]);
            atomicMin(&g_an[c0 + tid], ((unsigned int*)(sm + OFF_ANC))[tid]);
        }
    }
}

// ---------------------------------------------------------------------------
__global__ void final_kernel(float* __restrict__ out, int out_size)
{
    __shared__ float sl[256];
    __shared__ float sp[256];
    int tid = threadIdx.x;
    float loss = 0.f, prec = 0.f;
    for (int r = tid; r < NROWS; r += 256) {
        float ap = __uint_as_float(g_ap[r]);
        float an = __uint_as_float(g_an[r]);
        loss += fmaxf(ap - an + MARGIN, 0.f);
        prec += (an > ap) ? 1.f : 0.f;
    }
    sl[tid] = loss;
    sp[tid] = prec;
    __syncthreads();
    for (int s = 128; s; s >>= 1) {
        if (tid < s) { sl[tid] += sl[tid + s]; sp[tid] += sp[tid + s]; }
        __syncthreads();
    }
    if (tid == 0) {
        out[0] = sl[0] * (1.0f / NROWS);
        if (out_size > 1) out[1] = sp[0] * (1.0f / NROWS);
    }
}

// ---------------------------------------------------------------------------
extern "C" void kernel_launch(void* const* d_in, const int* in_sizes, int n_in,
                              void* d_out, int out_size)
{
    const float* x   = (const float*)d_in[0];
    const void*  tgt = d_in[1];
    float*       out = (float*)d_out;

    cudaFuncSetAttribute(tile_kernel, cudaFuncAttributeMaxDynamicSharedMemorySize, SMEM_TOTAL);

    init_kernel<<<1, 1>>>();
    prep_kernel<<<NROWS / 8, 256>>>(x, (const int*)tgt);
    convert_kernel<<<NROWS / 256, 256>>>(tgt);

    dim3 grid(NROWS / BN, NROWS / BM);   // (64, 64); lower triangle exits early
    tile_kernel<<<grid, 256, SMEM_TOTAL>>>();

    final_kernel<<<1, 256>>>(out, out_size);
}